// round 14
// baseline (speedup 1.0000x reference)
#include <cuda_runtime.h>
#include <cuda_bf16.h>
#include <cstdint>

// Problem constants
#define N_HOST 20000
#define N_FLOW 200000
#define NE     600000
#define D_IN   64
#define D_H    128
#define D_OUT  32

typedef unsigned long long ull;

#if defined(__CUDA_ARCH_FEAT_SM103_ALL) || defined(__CUDA_ARCH_FEAT_SM100_ALL) || defined(__CUDA_ARCH_FEAT_SM101_ALL)
#define HAS_TCGEN05 1
#else
#define HAS_TCGEN05 0
#endif

// ---------------- scratch ----------------
__device__ float g_aggX [(size_t)N_FLOW * D_IN];
__device__ float g_cntF [N_FLOW];
__device__ float g_aggH [(size_t)N_HOST * D_IN];
__device__ float g_cntH [N_HOST];
__device__ float g_th1  [(size_t)N_HOST * D_H];
__device__ float g_agg2 [(size_t)N_FLOW * D_H];

extern __shared__ char smem_raw[];

// ---------------- generic helpers ----------------
__device__ __forceinline__ float lrelu(float v) { return v > 0.f ? v : 0.01f * v; }

__device__ __forceinline__ uint32_t smem_u32(const void* p) {
    uint32_t a;
    asm("{ .reg .u64 t; cvta.to.shared.u64 t, %1; cvt.u32.u64 %0, t; }" : "=r"(a) : "l"(p));
    return a;
}

// ---------------- f32x2 packed-FMA helpers (fallback path) ----------------
__device__ __forceinline__ ull dup2(float x) {
    ull r; asm("mov.b64 %0, {%1, %1};" : "=l"(r) : "f"(x)); return r;
}
__device__ __forceinline__ void ffma2(ull& acc, ull a, ull b) {
    asm("fma.rn.f32x2 %0, %1, %2, %0;" : "+l"(acc) : "l"(a), "l"(b));
}

template <int K, int AP>
__device__ __forceinline__ void mma_tile(const float* __restrict__ As,
                                         const float* __restrict__ Ws,
                                         int tr8, int tc8, ull acc[8][4])
{
#pragma unroll 4
    for (int kk = 0; kk < K; kk++) {
        const ulonglong2* wp = reinterpret_cast<const ulonglong2*>(Ws + kk * 128 + tc8);
        ulonglong2 w01 = wp[0];
        ulonglong2 w23 = wp[1];
        ull ad[8];
#pragma unroll
        for (int i = 0; i < 8; i++) ad[i] = dup2(As[(tr8 + i) * AP + kk]);
#pragma unroll
        for (int i = 0; i < 8; i++) {
            ffma2(acc[i][0], ad[i], w01.x);
            ffma2(acc[i][1], ad[i], w01.y);
            ffma2(acc[i][2], ad[i], w23.x);
            ffma2(acc[i][3], ad[i], w23.y);
        }
    }
}
__device__ __forceinline__ void zero_acc(ull acc[8][4]) {
#pragma unroll
    for (int i = 0; i < 8; i++)
#pragma unroll
        for (int p = 0; p < 4; p++) acc[i][p] = 0ull;
}

// ---------------- tcgen05 helpers ----------------
#if HAS_TCGEN05
__device__ __forceinline__ bool elect1() {
    uint32_t p;
    asm volatile("{\n\t.reg .pred p;\n\telect.sync _|p, 0xFFFFFFFF;\n\tselp.b32 %0,1,0,p;\n\t}" : "=r"(p));
    return p != 0;
}
__device__ __forceinline__ ull mkdesc(uint32_t addr) {
    return 0x4000404000010000ull | ((ull)(addr >> 4) & 0x3FFFull);
}
__device__ __forceinline__ void mma_ts_f16(uint32_t d, uint32_t a, ull bd, uint32_t idesc, uint32_t acc) {
    asm volatile(
        "{\n\t.reg .pred p;\n\tsetp.ne.u32 p, %5, 0;\n\t"
        "tcgen05.mma.cta_group::1.kind::f16 [%0], [%1], %2, %3, {%4,%4,%4,%4}, p;\n\t}"
        :: "r"(d), "r"(a), "l"(bd), "r"(idesc), "r"(0u), "r"(acc) : "memory");
}
__device__ __forceinline__ void tc_commit(uint32_t mbar) {
    asm volatile("tcgen05.commit.cta_group::1.mbarrier::arrive::one.shared::cluster.b64 [%0];"
                 :: "r"(mbar) : "memory");
}
__device__ __forceinline__ void mbar_init(uint32_t a, uint32_t cnt) {
    asm volatile("mbarrier.init.shared.b64 [%0], %1;" :: "r"(a), "r"(cnt) : "memory");
}
__device__ __forceinline__ void mbar_wait(uint32_t a, uint32_t ph) {
    asm volatile(
        "{\n\t.reg .pred P;\n\tLW%=:\n\t"
        "mbarrier.try_wait.parity.acquire.cta.shared::cta.b64 P, [%0], %1;\n\t"
        "@!P bra LW%=;\n\t}"
        :: "r"(a), "r"(ph) : "memory");
}
#define TC_WAIT_LD()   asm volatile("tcgen05.wait::ld.sync.aligned;" ::: "memory")
#define TC_WAIT_ST()   asm volatile("tcgen05.wait::st.sync.aligned;" ::: "memory")
#define TC_FENCE_B()   asm volatile("tcgen05.fence::before_thread_sync;" ::: "memory")
#define TC_FENCE_A()   asm volatile("tcgen05.fence::after_thread_sync;" ::: "memory")
#define FENCE_PROXY()  asm volatile("fence.proxy.async.shared::cta;" ::: "memory")

__device__ __forceinline__ void ldtm32(uint32_t* r, uint32_t a) {
    asm volatile(
        "tcgen05.ld.sync.aligned.32x32b.x32.b32 "
        "{%0,%1,%2,%3,%4,%5,%6,%7,%8,%9,%10,%11,%12,%13,%14,%15,"
        "%16,%17,%18,%19,%20,%21,%22,%23,%24,%25,%26,%27,%28,%29,%30,%31}, [%32];"
        : "=r"(r[0]), "=r"(r[1]), "=r"(r[2]), "=r"(r[3]), "=r"(r[4]), "=r"(r[5]), "=r"(r[6]), "=r"(r[7]),
          "=r"(r[8]), "=r"(r[9]), "=r"(r[10]), "=r"(r[11]), "=r"(r[12]), "=r"(r[13]), "=r"(r[14]), "=r"(r[15]),
          "=r"(r[16]), "=r"(r[17]), "=r"(r[18]), "=r"(r[19]), "=r"(r[20]), "=r"(r[21]), "=r"(r[22]), "=r"(r[23]),
          "=r"(r[24]), "=r"(r[25]), "=r"(r[26]), "=r"(r[27]), "=r"(r[28]), "=r"(r[29]), "=r"(r[30]), "=r"(r[31])
        : "r"(a));
}
__device__ __forceinline__ void sttm_x8(uint32_t a, const uint32_t* r) {
    asm volatile(
        "tcgen05.st.sync.aligned.32x32b.x8.b32 [%0], {%1,%2,%3,%4,%5,%6,%7,%8};"
        :: "r"(a), "r"(r[0]), "r"(r[1]), "r"(r[2]), "r"(r[3]),
           "r"(r[4]), "r"(r[5]), "r"(r[6]), "r"(r[7]) : "memory");
}
__device__ __forceinline__ void sttm_x16(uint32_t a, const uint32_t* r) {
    asm volatile(
        "tcgen05.st.sync.aligned.32x32b.x16.b32 [%0], "
        "{%1,%2,%3,%4,%5,%6,%7,%8,%9,%10,%11,%12,%13,%14,%15,%16};"
        :: "r"(a), "r"(r[0]), "r"(r[1]), "r"(r[2]), "r"(r[3]),
           "r"(r[4]), "r"(r[5]), "r"(r[6]), "r"(r[7]),
           "r"(r[8]), "r"(r[9]), "r"(r[10]), "r"(r[11]),
           "r"(r[12]), "r"(r[13]), "r"(r[14]), "r"(r[15]) : "memory");
}

__device__ __forceinline__ uint32_t swz_bf16(int row, int col, int nar) {
    uint32_t b = (uint32_t)((row >> 3) + (col >> 6) * nar) * 1024u
               + (uint32_t)(row & 7) * 128u + (uint32_t)(col & 63) * 2u;
    return b ^ ((b >> 3) & 0x70u);
}

__device__ __forceinline__ void pack_hilo(float v0, float v1, uint32_t& h, uint32_t& l) {
    asm("cvt.rn.bf16x2.f32 %0, %1, %2;" : "=r"(h) : "f"(v1), "f"(v0));
    float h0 = __uint_as_float(h << 16);
    float h1 = __uint_as_float(h & 0xffff0000u);
    asm("cvt.rn.bf16x2.f32 %0, %1, %2;" : "=r"(l) : "f"(v1 - h1), "f"(v0 - h0));
}
#endif  // HAS_TCGEN05

// ---------------- zero kernels ----------------
__global__ void k_zero_fh() {
    size_t i = (size_t)blockIdx.x * blockDim.x + threadIdx.x;
    size_t stride = (size_t)gridDim.x * blockDim.x;
    const float4 z = make_float4(0.f, 0.f, 0.f, 0.f);
    for (size_t k = i; k < ((size_t)N_HOST * D_IN) / 4; k += stride) ((float4*)g_aggH)[k] = z;
    for (size_t k = i; k < (size_t)N_HOST / 4; k += stride) ((float4*)g_cntH)[k] = z;
}
__global__ void k_zero_hf() {
    size_t i = (size_t)blockIdx.x * blockDim.x + threadIdx.x;
    size_t stride = (size_t)gridDim.x * blockDim.x;
    const float4 z = make_float4(0.f, 0.f, 0.f, 0.f);
    for (size_t k = i; k < ((size_t)N_FLOW * D_IN) / 4; k += stride) ((float4*)g_aggX)[k] = z;
    for (size_t k = i; k < (size_t)N_FLOW / 4; k += stride) ((float4*)g_cntF)[k] = z;
}
__global__ void k_zero_a2() {
    size_t i = (size_t)blockIdx.x * blockDim.x + threadIdx.x;
    size_t stride = (size_t)gridDim.x * blockDim.x;
    const float4 z = make_float4(0.f, 0.f, 0.f, 0.f);
    for (size_t k = i; k < ((size_t)N_FLOW * D_H) / 4; k += stride) ((float4*)g_agg2)[k] = z;
}

// ---------------- 64-dim edge scatter (2 independent edges per lane-group) ----------------
__global__ __launch_bounds__(256) void k_scatter64(
    const float* __restrict__ feat, const int* __restrict__ src,
    const int* __restrict__ dst, float* __restrict__ agg, float* __restrict__ cnt)
{
    const int HALF = NE / 2;
    int eloc = threadIdx.x >> 4;
    int lane = threadIdx.x & 15;
    int e = blockIdx.x * 16 + eloc;
    if (e >= HALF) return;
    int e1 = e + HALF;
    int s0 = __ldg(src + e),  d0 = __ldg(dst + e);
    int s1 = __ldg(src + e1), d1 = __ldg(dst + e1);
    float4 v0 = *(const float4*)(feat + (size_t)s0 * 64 + lane * 4);
    float4 v1 = *(const float4*)(feat + (size_t)s1 * 64 + lane * 4);
    float* p0 = agg + (size_t)d0 * 64 + lane * 4;
    float* p1 = agg + (size_t)d1 * 64 + lane * 4;
    asm volatile("red.global.add.v4.f32 [%0], {%1,%2,%3,%4};"
                 :: "l"(p0), "f"(v0.x), "f"(v0.y), "f"(v0.z), "f"(v0.w) : "memory");
    asm volatile("red.global.add.v4.f32 [%0], {%1,%2,%3,%4};"
                 :: "l"(p1), "f"(v1.x), "f"(v1.y), "f"(v1.z), "f"(v1.w) : "memory");
    if (lane == 0) { atomicAdd(cnt + d0, 1.0f); atomicAdd(cnt + d1, 1.0f); }
}

// ---------------- 128-dim scatter (2 independent edges per lane-group) ----------------
__global__ __launch_bounds__(256) void k_scatter128(
    const float* __restrict__ feat, const int* __restrict__ src,
    const int* __restrict__ dst, float* __restrict__ agg)
{
    const int HALF = NE / 2;
    int eloc = threadIdx.x >> 5;
    int lane = threadIdx.x & 31;
    int e = blockIdx.x * 8 + eloc;
    if (e >= HALF) return;
    int e1 = e + HALF;
    int s0 = __ldg(src + e),  d0 = __ldg(dst + e);
    int s1 = __ldg(src + e1), d1 = __ldg(dst + e1);
    float4 v0 = *(const float4*)(feat + (size_t)s0 * 128 + lane * 4);
    float4 v1 = *(const float4*)(feat + (size_t)s1 * 128 + lane * 4);
    float* p0 = agg + (size_t)d0 * 128 + lane * 4;
    float* p1 = agg + (size_t)d1 * 128 + lane * 4;
    asm volatile("red.global.add.v4.f32 [%0], {%1,%2,%3,%4};"
                 :: "l"(p0), "f"(v0.x), "f"(v0.y), "f"(v0.z), "f"(v0.w) : "memory");
    asm volatile("red.global.add.v4.f32 [%0], {%1,%2,%3,%4};"
                 :: "l"(p1), "f"(v1.x), "f"(v1.y), "f"(v1.z), "f"(v1.w) : "memory");
}

// ================= host chain: th1 = lrelu([aggH*inv|xh]@[W0l;W0r]+b0) @ W1l =================
struct HostSmem {            // FFMA2 fallback layout (also bounds the smem request)
    float Ws0[128 * 128];
    float Ws1[128 * 128];
    float Buf[128 * 132];
};
#define HOST_SMEM_REQ ((int)sizeof(HostSmem))

__global__ __launch_bounds__(256, 1) void k_host(
    const float* __restrict__ aggH, const float* __restrict__ cntH,
    const float* __restrict__ xh,
    const float* __restrict__ W0l, const float* __restrict__ W0r,
    const float* __restrict__ b0,
    const float* __restrict__ W1l,
    float* __restrict__ th1)
{
#if HAS_TCGEN05
    const int tid = threadIdx.x;
    const int wid = tid >> 5;
    const int lane = tid & 31;

    uint32_t raw = smem_u32(smem_raw);
    uint32_t base = (raw + 1023u) & ~1023u;
    char* sp = smem_raw + (base - raw);
    char* pW0H = sp;          char* pW0L = sp + 32768;
    char* pW1H = sp + 65536;  char* pW1L = sp + 98304;
    float* b0s = (float*)(sp + 131072);
    const uint32_t MB = base + 131584;
    const uint32_t TP = base + 131600;

    for (int i = tid; i < 128 * 128; i += 256) {
        int k = i >> 7, n = i & 127;
        float v = (k < 64) ? W0l[k * 128 + n] : W0r[(k - 64) * 128 + n];
        __nv_bfloat16 h = __float2bfloat16(v);
        __nv_bfloat16 l = __float2bfloat16(v - __bfloat162float(h));
        uint32_t o = swz_bf16(n, k, 16);
        *(__nv_bfloat16*)(pW0H + o) = h;
        *(__nv_bfloat16*)(pW0L + o) = l;
    }
    for (int i = tid; i < 128 * 128; i += 256) {
        int k = i >> 7, n = i & 127;
        float v = W1l[i];
        __nv_bfloat16 h = __float2bfloat16(v);
        __nv_bfloat16 l = __float2bfloat16(v - __bfloat162float(h));
        uint32_t o = swz_bf16(n, k, 16);
        *(__nv_bfloat16*)(pW1H + o) = h;
        *(__nv_bfloat16*)(pW1L + o) = l;
    }
    for (int i = tid; i < 128; i += 256) b0s[i] = b0[i];
    if (tid == 0) { mbar_init(MB, 1); mbar_init(MB + 8, 1); }
    if (wid == 0) {
        asm volatile("tcgen05.alloc.cta_group::1.sync.aligned.shared::cta.b32 [%0], %1;"
                     :: "r"(TP), "r"(256) : "memory");
        asm volatile("tcgen05.relinquish_alloc_permit.cta_group::1.sync.aligned;");
    }
    FENCE_PROXY();
    __syncthreads();
    uint32_t tmem;
    asm volatile("ld.shared.b32 %0, [%1];" : "=r"(tmem) : "r"(TP));

    const ull d0H = mkdesc(base), d0L = mkdesc(base + 32768);
    const ull d1H = mkdesc(base + 65536), d1L = mkdesc(base + 98304);
    const uint32_t idesc128 = 0x8200490u;
    const int BOW[8] = {0, 2, 4, 6, 1024, 1026, 1028, 1030};

    const int sub = wid & 3, half = wid >> 2;
    const int r = sub * 32 + lane;
    const uint32_t tm_row = (uint32_t)sub << 21;
    const int c0a = half * 32, c0b = 64 + half * 32;
    const uint32_t SA = tmem, SD = tmem + 128;

    const int NT = (N_HOST + 127) >> 7;    // 157
    int it = 0;
    for (int tile = blockIdx.x; tile < NT; tile += gridDim.x, ++it) {
        const int row0 = tile << 7;
        const int ge = row0 + r;
        const int gs = ge < N_HOST ? ge : N_HOST - 1;
        const int par = it & 1;

        float inv = 1.f / fmaxf(__ldg(cntH + gs), 1.f);
        {
            const float* src = half ? (xh + (size_t)gs * 64) : (aggH + (size_t)gs * 64);
            float sc = half ? 1.f : inv;
            uint32_t A0 = SA + (uint32_t)(half * 32) + tm_row;
#pragma unroll
            for (int q = 0; q < 4; q++) {
                const float4* p4 = (const float4*)(src + q * 16);
                float4 f0 = p4[0], f1 = p4[1], f2 = p4[2], f3 = p4[3];
                float e[16] = {f0.x, f0.y, f0.z, f0.w, f1.x, f1.y, f1.z, f1.w,
                               f2.x, f2.y, f2.z, f2.w, f3.x, f3.y, f3.z, f3.w};
                uint32_t hi[8], lo[8];
#pragma unroll
                for (int i = 0; i < 8; i++) pack_hilo(e[2 * i] * sc, e[2 * i + 1] * sc, hi[i], lo[i]);
                sttm_x8(A0 + q * 8, hi);
                sttm_x8(A0 + 64 + q * 8, lo);
            }
            TC_WAIT_ST();
        }
        TC_FENCE_B();
        __syncthreads();

        if (wid == 0) {
            TC_FENCE_A();
            if (elect1()) {
#pragma unroll
                for (int s = 0; s < 8; s++) mma_ts_f16(SD, SA + s * 8, d0H + BOW[s], idesc128, s > 0);
#pragma unroll
                for (int s = 0; s < 8; s++) mma_ts_f16(SD, SA + s * 8, d0L + BOW[s], idesc128, 1);
#pragma unroll
                for (int s = 0; s < 8; s++) mma_ts_f16(SD, SA + 64 + s * 8, d0H + BOW[s], idesc128, 1);
                tc_commit(MB);
            }
        }
        mbar_wait(MB, par);
        TC_FENCE_A();

        {
            uint32_t dr[32], hi[16], lo[16];
            ldtm32(dr, SD + c0a + tm_row);
            TC_WAIT_LD();
#pragma unroll
            for (int j = 0; j < 32; j += 2) {
                float v0 = lrelu(__uint_as_float(dr[j])     + b0s[c0a + j]);
                float v1 = lrelu(__uint_as_float(dr[j + 1]) + b0s[c0a + j + 1]);
                pack_hilo(v0, v1, hi[j >> 1], lo[j >> 1]);
            }
            sttm_x16(SA + (c0a >> 1) + tm_row, hi);
            sttm_x16(SA + 64 + (c0a >> 1) + tm_row, lo);
            ldtm32(dr, SD + c0b + tm_row);
            TC_WAIT_LD();
#pragma unroll
            for (int j = 0; j < 32; j += 2) {
                float v0 = lrelu(__uint_as_float(dr[j])     + b0s[c0b + j]);
                float v1 = lrelu(__uint_as_float(dr[j + 1]) + b0s[c0b + j + 1]);
                pack_hilo(v0, v1, hi[j >> 1], lo[j >> 1]);
            }
            sttm_x16(SA + (c0b >> 1) + tm_row, hi);
            sttm_x16(SA + 64 + (c0b >> 1) + tm_row, lo);
            TC_WAIT_ST();
        }
        TC_FENCE_B();
        __syncthreads();

        if (wid == 0) {
            TC_FENCE_A();
            if (elect1()) {
#pragma unroll
                for (int s = 0; s < 8; s++) mma_ts_f16(SD, SA + s * 8, d1H + BOW[s], idesc128, s > 0);
#pragma unroll
                for (int s = 0; s < 8; s++) mma_ts_f16(SD, SA + s * 8, d1L + BOW[s], idesc128, 1);
#pragma unroll
                for (int s = 0; s < 8; s++) mma_ts_f16(SD, SA + 64 + s * 8, d1H + BOW[s], idesc128, 1);
                tc_commit(MB + 8);
            }
        }
        mbar_wait(MB + 8, par);
        TC_FENCE_A();

        {
            uint32_t dr[32];
            ldtm32(dr, SD + c0a + tm_row);
            TC_WAIT_LD();
            if (ge < N_HOST) {
                float* tp = th1 + (size_t)ge * 128 + c0a;
#pragma unroll
                for (int j = 0; j < 32; j += 4)
                    *(float4*)(tp + j) = make_float4(
                        __uint_as_float(dr[j]), __uint_as_float(dr[j + 1]),
                        __uint_as_float(dr[j + 2]), __uint_as_float(dr[j + 3]));
            }
            ldtm32(dr, SD + c0b + tm_row);
            TC_WAIT_LD();
            if (ge < N_HOST) {
                float* tp = th1 + (size_t)ge * 128 + c0b;
#pragma unroll
                for (int j = 0; j < 32; j += 4)
                    *(float4*)(tp + j) = make_float4(
                        __uint_as_float(dr[j]), __uint_as_float(dr[j + 1]),
                        __uint_as_float(dr[j + 2]), __uint_as_float(dr[j + 3]));
            }
        }
        TC_FENCE_B();
    }

    __syncthreads();
    if (wid == 0) {
        asm volatile("tcgen05.dealloc.cta_group::1.sync.aligned.b32 %0, %1;" :: "r"(tmem), "r"(256));
    }
#else
    HostSmem* S = reinterpret_cast<HostSmem*>(smem_raw);
    const int tid = threadIdx.x;
    for (int i = tid; i < 128 * 128; i += 256) {
        int k = i >> 7, n = i & 127;
        S->Ws0[i] = (k < 64) ? W0l[k * 128 + n] : W0r[(k - 64) * 128 + n];
    }
    for (int f = tid; f < 128 * 128 / 4; f += 256) ((float4*)S->Ws1)[f] = ((const float4*)W1l)[f];

    const int tr8 = (tid >> 4) * 8;
    const int tc8 = (tid & 15) * 8;
    float b0r[8];
#pragma unroll
    for (int j = 0; j < 8; j++) b0r[j] = b0[tc8 + j];

    const int NT = (N_HOST + 127) / 128;
    for (int tile = blockIdx.x; tile < NT; tile += gridDim.x) {
        const int row0 = tile * 128;
        __syncthreads();
        for (int f = tid; f < 4096; f += 256) {
            int r = f >> 5, cc = (f & 31) * 4;
            int gr = row0 + r;
            if (gr >= N_HOST) continue;
            float4 v;
            if (cc < 64) {
                float inv = 1.f / fmaxf(__ldg(cntH + gr), 1.f);
                v = *(const float4*)(aggH + (size_t)gr * 64 + cc);
                v.x *= inv; v.y *= inv; v.z *= inv; v.w *= inv;
            } else {
                v = *(const float4*)(xh + (size_t)gr * 64 + (cc - 64));
            }
            *(float4*)(&S->Buf[r * 132 + cc]) = v;
        }
        __syncthreads();

        ull acc[8][4];
        zero_acc(acc);
        mma_tile<128, 132>(S->Buf, S->Ws0, tr8, tc8, acc);
        __syncthreads();
#pragma unroll
        for (int i = 0; i < 8; i++) {
#pragma unroll
            for (int p = 0; p < 4; p++) {
                float2 v = *reinterpret_cast<float2*>(&acc[i][p]);
                S->Buf[(tr8 + i) * 132 + tc8 + 2 * p]     = lrelu(v.x + b0r[2 * p]);
                S->Buf[(tr8 + i) * 132 + tc8 + 2 * p + 1] = lrelu(v.y + b0r[2 * p + 1]);
            }
        }
        __syncthreads();

        zero_acc(acc);
        mma_tile<128, 132>(S->Buf, S->Ws1, tr8, tc8, acc);
#pragma unroll
        for (int i = 0; i < 8; i++) {
            int gr = row0 + tr8 + i;
            if (gr >= N_HOST) continue;
            float2 v0 = *reinterpret_cast<float2*>(&acc[i][0]);
            float2 v1 = *reinterpret_cast<float2*>(&acc[i][1]);
            float2 v2 = *reinterpret_cast<float2*>(&acc[i][2]);
            float2 v3 = *reinterpret_cast<float2*>(&acc[i][3]);
            *(float4*)(th1 + (size_t)gr * 128 + tc8)     = make_float4(v0.x, v0.y, v1.x, v1.y);
            *(float4*)(th1 + (size_t)gr * 128 + tc8 + 4) = make_float4(v2.x, v2.y, v3.x, v3.y);
        }
    }
#endif
}

// ================= flow chain (paired-tile tcgen05 pipeline) =================
#define O_W01H 0
#define O_W01L 32768
#define O_W1H  65536
#define O_W1L  98304
#define O_WOH  131072
#define O_WOL  139264
#define O_B0   147456
#define O_B1   147968
#define O_BO   148480
#define O_MB   148608
#define O_TP   148656
#define TM_SA0 0
#define TM_SA1 128
#define TM_SD0 256
#define TM_SD1 384

#define FLOW_SMEM_REQ 231936

__global__ __launch_bounds__(256, 1)
void k_flow_tc(const float* __restrict__ xf,
               const float* __restrict__ aggX, const float* __restrict__ agg2,
               const float* __restrict__ cnt,
               const float* __restrict__ W0r, const float* __restrict__ W0l,
               const float* __restrict__ b0,
               const float* __restrict__ W1r, const float* __restrict__ b1,
               const float* __restrict__ Wo,  const float* __restrict__ bo,
               float* __restrict__ out)
{
#if HAS_TCGEN05
    const int tid = threadIdx.x;
    const int wid = tid >> 5;
    const int lane = tid & 31;

    uint32_t raw = smem_u32(smem_raw);
    uint32_t base = (raw + 1023u) & ~1023u;
    char* sp = smem_raw + (base - raw);

    char* pW01H = sp + O_W01H; char* pW01L = sp + O_W01L;
    char* pW1H  = sp + O_W1H;  char* pW1L  = sp + O_W1L;
    char* pWOH  = sp + O_WOH;  char* pWOL  = sp + O_WOL;
    float* b0s = (float*)(sp + O_B0);
    float* b1s = (float*)(sp + O_B1);
    float* bos = (float*)(sp + O_BO);
    const uint32_t MB = base + O_MB;

    for (int i = tid; i < 128 * 128; i += 256) {
        int k = i >> 7, n = i & 127;
        float v = (k < 64) ? W0r[k * 128 + n] : W0l[(k - 64) * 128 + n];
        __nv_bfloat16 h = __float2bfloat16(v);
        __nv_bfloat16 l = __float2bfloat16(v - __bfloat162float(h));
        uint32_t o = swz_bf16(n, k, 16);
        *(__nv_bfloat16*)(pW01H + o) = h;
        *(__nv_bfloat16*)(pW01L + o) = l;
    }
    for (int i = tid; i < 128 * 128; i += 256) {
        int k = i >> 7, n = i & 127;
        float v = W1r[i];
        __nv_bfloat16 h = __float2bfloat16(v);
        __nv_bfloat16 l = __float2bfloat16(v - __bfloat162float(h));
        uint32_t o = swz_bf16(n, k, 16);
        *(__nv_bfloat16*)(pW1H + o) = h;
        *(__nv_bfloat16*)(pW1L + o) = l;
    }
    for (int i = tid; i < 128 * 32; i += 256) {
        int k = i >> 5, n = i & 31;
        float v = Wo[i];
        __nv_bfloat16 h = __float2bfloat16(v);
        __nv_bfloat16 l = __float2bfloat16(v - __bfloat162float(h));
        uint32_t o = swz_bf16(n, k, 4);
        *(__nv_bfloat16*)(pWOH + o) = h;
        *(__nv_bfloat16*)(pWOL + o) = l;
    }
    for (int i = tid; i < 128; i += 256) { b0s[i] = b0[i]; b1s[i] = b1[i]; }
    if (tid < 32) bos[tid] = bo[tid];
    if (tid == 0) {
#pragma unroll
        for (int m = 0; m < 6; m++) mbar_init(MB + 8 * m, 1);
    }
    if (wid == 0) {
        asm volatile("tcgen05.alloc.cta_group::1.sync.aligned.shared::cta.b32 [%0], %1;"
                     :: "r"(base + O_TP), "r"(512) : "memory");
    }
    FENCE_PROXY();
    __syncthreads();
    uint32_t tmem;
    asm volatile("ld.shared.b32 %0, [%1];" : "=r"(tmem) : "r"(base + O_TP));

    const ull d0H = mkdesc(base + O_W01H), d0L = mkdesc(base + O_W01L);
    const ull d1H = mkdesc(base + O_W1H),  d1L = mkdesc(base + O_W1L);
    const ull dOH = mkdesc(base + O_WOH),  dOL = mkdesc(base + O_WOL);
    const uint32_t idesc128 = 0x8200490u;
    const uint32_t idesc32  = 0x8080490u;

    const int sub = wid & 3, half = wid >> 2;
    const int r = sub * 32 + lane;
    const uint32_t tm_row = (uint32_t)sub << 21;
    const int c0a = half * 32;
    const int c0b = 64 + half * 32;

    const uint32_t SA0 = tmem + TM_SA0, SA1 = tmem + TM_SA1;
    const uint32_t SD0 = tmem + TM_SD0, SD1 = tmem + TM_SD1;

    const int NT = (N_FLOW + 127) >> 7;
    const int NP = (NT + 1) >> 1;

    const int BOW[8] = {0, 2, 4, 6, 1024, 1026, 1028, 1030};
    const int BOO[8] = {0, 2, 4, 6, 256, 258, 260, 262};

    auto load_A = [&](int row0n, uint32_t slot) -> float {
        int gn = row0n + r;
        int gs = gn < N_FLOW ? gn : N_FLOW - 1;
        float inv = 1.f / fmaxf(__ldg(cnt + gs), 1.f);
        const float* src = half ? (aggX + (size_t)gs * 64) : (xf + (size_t)gs * 64);
        float sc = half ? inv : 1.f;
        uint32_t A0 = slot + (uint32_t)(half * 32) + tm_row;
#pragma unroll
        for (int q = 0; q < 4; q++) {
            const float4* p4 = (const float4*)(src + q * 16);
            float4 f0 = p4[0], f1 = p4[1], f2 = p4[2], f3 = p4[3];
            float e[16] = {f0.x, f0.y, f0.z, f0.w, f1.x, f1.y, f1.z, f1.w,
                           f2.x, f2.y, f2.z, f2.w, f3.x, f3.y, f3.z, f3.w};
            uint32_t hi[8], lo[8];
#pragma unroll
            for (int i = 0; i < 8; i++) pack_hilo(e[2 * i] * sc, e[2 * i + 1] * sc, hi[i], lo[i]);
            sttm_x8(A0 + q * 8, hi);
            sttm_x8(A0 + 64 + q * 8, lo);
        }
        TC_WAIT_ST();
        return inv;
    };

    auto mma_phase = [&](uint32_t a0, uint32_t dD, ull bh, ull bl, const int* BO, uint32_t idesc) {
#pragma unroll
        for (int s = 0; s < 8; s++) mma_ts_f16(dD, a0 + s * 8, bh + BO[s], idesc, s > 0);
#pragma unroll
        for (int s = 0; s < 8; s++) mma_ts_f16(dD, a0 + s * 8, bl + BO[s], idesc, 1);
#pragma unroll
        for (int s = 0; s < 8; s++) mma_ts_f16(dD, a0 + 64 + s * 8, bh + BO[s], idesc, 1);
    };

    auto epi1 = [&](uint32_t dSlot, uint32_t aSlot) {
        uint32_t dr[32], hi[16], lo[16];
        ldtm32(dr, dSlot + c0a + tm_row);
        TC_WAIT_LD();
#pragma unroll
        for (int j = 0; j < 32; j += 2) {
            float v0 = lrelu(__uint_as_float(dr[j])     + b0s[c0a + j]);
            float v1 = lrelu(__uint_as_float(dr[j + 1]) + b0s[c0a + j + 1]);
            pack_hilo(v0, v1, hi[j >> 1], lo[j >> 1]);
        }
        sttm_x16(aSlot + (c0a >> 1) + tm_row, hi);
        sttm_x16(aSlot + 64 + (c0a >> 1) + tm_row, lo);
        ldtm32(dr, dSlot + c0b + tm_row);
        TC_WAIT_LD();
#pragma unroll
        for (int j = 0; j < 32; j += 2) {
            float v0 = lrelu(__uint_as_float(dr[j])     + b0s[c0b + j]);
            float v1 = lrelu(__uint_as_float(dr[j + 1]) + b0s[c0b + j + 1]);
            pack_hilo(v0, v1, hi[j >> 1], lo[j >> 1]);
        }
        sttm_x16(aSlot + (c0b >> 1) + tm_row, hi);
        sttm_x16(aSlot + 64 + (c0b >> 1) + tm_row, lo);
        TC_WAIT_ST();
    };

    auto prefetch2 = [&](int ge, float4* q0, float4* q1) {
        int gs = ge < N_FLOW ? ge : N_FLOW - 1;
        const float4* ap = (const float4*)(agg2 + (size_t)gs * 128);
#pragma unroll
        for (int i = 0; i < 8; i++) q0[i] = ap[(c0a >> 2) + i];
#pragma unroll
        for (int i = 0; i < 8; i++) q1[i] = ap[(c0b >> 2) + i];
    };

    auto epi2 = [&](uint32_t dSlot, uint32_t aSlot, const float4* q0, const float4* q1, float inv) {
        uint32_t dr[32], hi[16], lo[16];
        ldtm32(dr, dSlot + c0a + tm_row);
        TC_WAIT_LD();
#pragma unroll
        for (int j = 0; j < 32; j += 4) {
            float4 av = q0[j >> 2];
            float v0 = lrelu(__uint_as_float(dr[j])     + av.x * inv + b1s[c0a + j]);
            float v1 = lrelu(__uint_as_float(dr[j + 1]) + av.y * inv + b1s[c0a + j + 1]);
            float v2 = lrelu(__uint_as_float(dr[j + 2]) + av.z * inv + b1s[c0a + j + 2]);
            float v3 = lrelu(__uint_as_float(dr[j + 3]) + av.w * inv + b1s[c0a + j + 3]);
            pack_hilo(v0, v1, hi[j >> 1], lo[j >> 1]);
            pack_hilo(v2, v3, hi[(j >> 1) + 1], lo[(j >> 1) + 1]);
        }
        sttm_x16(aSlot + (c0a >> 1) + tm_row, hi);
        sttm_x16(aSlot + 64 + (c0a >> 1) + tm_row, lo);
        ldtm32(dr, dSlot + c0b + tm_row);
        TC_WAIT_LD();
#pragma unroll
        for (int j = 0; j < 32; j += 4) {
            float4 av = q1[j >> 2];
            float v0 = lrelu(__uint_as_float(dr[j])     + av.x * inv + b1s[c0b + j]);
            float v1 = lrelu(__uint_as_float(dr[j + 1]) + av.y * inv + b1s[c0b + j + 1]);
            float v2 = lrelu(__uint_as_float(dr[j + 2]) + av.z * inv + b1s[c0b + j + 2]);
            float v3 = lrelu(__uint_as_float(dr[j + 3]) + av.w * inv + b1s[c0b + j + 3]);
            pack_hilo(v0, v1, hi[j >> 1], lo[j >> 1]);
            pack_hilo(v2, v3, hi[(j >> 1) + 1], lo[(j >> 1) + 1]);
        }
        sttm_x16(aSlot + (c0b >> 1) + tm_row, hi);
        sttm_x16(aSlot + 64 + (c0b >> 1) + tm_row, lo);
        TC_WAIT_ST();
    };

    auto epi3 = [&](uint32_t dSlot, int ge) {
        if (wid >= 4) return;
        uint32_t dr[32];
        ldtm32(dr, dSlot + tm_row);
        TC_WAIT_LD();
        if (ge < N_FLOW) {
            float* op = out + (size_t)ge * 32;
#pragma unroll
            for (int c = 0; c < 32; c += 4) {
                *(float4*)(op + c) = make_float4(
                    __uint_as_float(dr[c])     + bos[c],
                    __uint_as_float(dr[c + 1]) + bos[c + 1],
                    __uint_as_float(dr[c + 2]) + bos[c + 2],
                    __uint_as_float(dr[c + 3]) + bos[c + 3]);
            }
        }
    };

    int it = 0;
    for (int p = blockIdx.x; p < NP; p += gridDim.x, ++it) {
        const int tileA = 2 * p, tileB = tileA + 1;
        const bool vB = tileB < NT;
        const int row0A = tileA << 7, row0B = tileB << 7;
        const int geA = row0A + r, geB = row0B + r;
        const int par = it & 1;
        __syncthreads();

        float invA = load_A(row0A, SA0);
        float invB = 1.f;
        if (vB) invB = load_A(row0B, SA1);
        TC_FENCE_B();
        __syncthreads();

        if (wid == 0) {
            TC_FENCE_A();
            if (elect1()) {
                mma_phase(SA0, SD0, d0H, d0L, BOW, idesc128); tc_commit(MB + 0);
                if (vB) { mma_phase(SA1, SD1, d0H, d0L, BOW, idesc128); tc_commit(MB + 8); }
            }
        }

        mbar_wait(MB + 0, par); TC_FENCE_A();
        epi1(SD0, SA0);
        TC_FENCE_B(); __syncthreads();
        if (wid == 0) {
            TC_FENCE_A();
            if (elect1()) { mma_phase(SA0, SD0, d1H, d1L, BOW, idesc128); tc_commit(MB + 16); }
        }
        float4 qa0[8], qa1[8];
        prefetch2(geA, qa0, qa1);

        if (vB) {
            mbar_wait(MB + 8, par); TC_FENCE_A();
            epi1(SD1, SA1);
            TC_FENCE_B(); __syncthreads();
            if (wid == 0) {
                TC_FENCE_A();
                if (elect1()) { mma_phase(SA1, SD1, d1H, d1L, BOW, idesc128); tc_commit(MB + 24); }
            }
        }

        mbar_wait(MB + 16, par); TC_FENCE_A();
        epi2(SD0, SA0, qa0, qa1, invA);
        TC_FENCE_B(); __syncthreads();
        if (wid == 0) {
            TC_FENCE_A();
            if (elect1()) { mma_phase(SA0, SD0, dOH, dOL, BOO, idesc32); tc_commit(MB + 32); }
        }

        if (vB) {
            float4 qb0[8], qb1[8];
            prefetch2(geB, qb0, qb1);
            mbar_wait(MB + 24, par); TC_FENCE_A();
            epi2(SD1, SA1, qb0, qb1, invB);
            TC_FENCE_B(); __syncthreads();
            if (wid == 0) {
                TC_FENCE_A();
                if (elect1()) { mma_phase(SA1, SD1, dOH, dOL, BOO, idesc32); tc_commit(MB + 40); }
            }
        }

        mbar_wait(MB + 32, par); TC_FENCE_A();
        epi3(SD0, geA);
        if (vB) {
            mbar_wait(MB + 40, par); TC_FENCE_A();
            epi3(SD1, geB);
        }
        TC_FENCE_B();
    }

    __syncthreads();
    if (wid == 0) {
        asm volatile("tcgen05.relinquish_alloc_permit.cta_group::1.sync.aligned;");
        asm volatile("tcgen05.dealloc.cta_group::1.sync.aligned.b32 %0, %1;" :: "r"(tmem), "r"(512));
    }
#else
    // ==================== FFMA2 fallback path ====================
    float* Ws0a = (float*)smem_raw;
    float* Ws0b = Ws0a + 64 * 128;
    float* Ws1  = Ws0b + 64 * 128;
    float* Asf  = Ws1 + 128 * 128;
    float* H    = Asf + 128 * 68;

    const int tid = threadIdx.x;
    for (int f = tid; f < 64 * 128 / 4; f += 256) {
        ((float4*)Ws0a)[f] = ((const float4*)W0r)[f];
        ((float4*)Ws0b)[f] = ((const float4*)W0l)[f];
    }
    for (int f = tid; f < 128 * 128 / 4; f += 256) ((float4*)Ws1)[f] = ((const float4*)W1r)[f];

    const int tr8 = (tid >> 4) * 8;
    const int tc8 = (tid & 15) * 8;
    float b0r[8], b1r[8];
#pragma unroll
    for (int j = 0; j < 8; j++) { b0r[j] = b0[tc8 + j]; b1r[j] = b1[tc8 + j]; }
    const int r4 = (tid >> 3) * 4;
    const int c4 = (tid & 7) * 4;
    float bor[4];
#pragma unroll
    for (int j = 0; j < 4; j++) bor[j] = bo[c4 + j];

    const int NT = (N_FLOW + 127) / 128;
    for (int tile = blockIdx.x; tile < NT; tile += gridDim.x) {
        const int row0 = tile * 128;
        __syncthreads();
        for (int f = tid; f < 2048; f += 256) {
            int r = f >> 4, cc = (f & 15) * 4;
            int gr = row0 + r;
            if (gr < N_FLOW)
                *(float4*)(Asf + r * 68 + cc) = *(const float4*)(xf + (size_t)gr * 64 + cc);
        }
        __syncthreads();

        ull acc[8][4];
        zero_acc(acc);
        mma_tile<64, 68>(Asf, Ws0a, tr8, tc8, acc);
        __syncthreads();
        for (int f = tid; f < 2048; f += 256) {
            int r = f >> 4, cc = (f & 15) * 4;
            int gr = row0 + r;
            if (gr < N_FLOW) {
                float inv = 1.f / fmaxf(__ldg(cnt + gr), 1.f);
                float4 v = *(const float4*)(aggX + (size_t)gr * 64 + cc);
                v.x *= inv; v.y *= inv; v.z *= inv; v.w *= inv;
                *(float4*)(Asf + r * 68 + cc) = v;
            }
        }
        __syncthreads();
        mma_tile<64, 68>(Asf, Ws0b, tr8, tc8, acc);

#pragma unroll
        for (int i = 0; i < 8; i++) {
            int gr = row0 + tr8 + i;
            if (gr >= N_FLOW) continue;
#pragma unroll
            for (int p = 0; p < 4; p++) {
                float2 v = *reinterpret_cast<float2*>(&acc[i][p]);
                H[(tr8 + i) * 129 + tc8 + 2 * p]     = lrelu(v.x + b0r[2 * p]);
                H[(tr8 + i) * 129 + tc8 + 2 * p + 1] = lrelu(v.y + b0r[2 * p + 1]);
            }
        }
        __syncthreads();

        zero_acc(acc);
        mma_tile<128, 129>(H, Ws1, tr8, tc8, acc);
        __syncthreads();
#pragma unroll
        for (int i = 0; i < 8; i++) {
            int gr = row0 + tr8 + i;
            if (gr >= N_FLOW) continue;
            float inv = 1.f / fmaxf(__ldg(cnt + gr), 1.f);
            float4 p0 = *(const float4*)(agg2 + (size_t)gr * 128 + tc8);
            float4 p1 = *(const float4*)(agg2 + (size_t)gr * 128 + tc8 + 4);
            float pv[8] = {p0.x, p0.y, p0.z, p0.w, p1.x, p1.y, p1.z, p1.w};
#pragma unroll
            for (int p = 0; p < 4; p++) {
                float2 v = *reinterpret_cast<float2*>(&acc[i][p]);
                H[(tr8 + i) * 129 + tc8 + 2 * p]     = lrelu(v.x + pv[2 * p] * inv + b1r[2 * p]);
                H[(tr8 + i) * 129 + tc8 + 2 * p + 1] = lrelu(v.y + pv[2 * p + 1] * inv + b1r[2 * p + 1]);
            }
        }
        __syncthreads();

        ull acc3[4][2];
#pragma unroll
        for (int i = 0; i < 4; i++) { acc3[i][0] = 0ull; acc3[i][1] = 0ull; }
#pragma unroll 4
        for (int kk = 0; kk < 128; kk++) {
            float4 wv = __ldg((const float4*)(Wo + kk * 32 + c4));
            ull wx, wy;
            asm("mov.b64 %0, {%1, %2};" : "=l"(wx) : "f"(wv.x), "f"(wv.y));
            asm("mov.b64 %0, {%1, %2};" : "=l"(wy) : "f"(wv.z), "f"(wv.w));
#pragma unroll
            for (int i = 0; i < 4; i++) {
                ull ad = dup2(H[(r4 + i) * 129 + kk]);
                ffma2(acc3[i][0], ad, wx);
                ffma2(acc3[i][1], ad, wy);
            }
        }
#pragma unroll
        for (int i = 0; i < 4; i++) {
            int gr = row0 + r4 + i;
            if (gr >= N_FLOW) continue;
            float2 v0 = *reinterpret_cast<float2*>(&acc3[i][0]);
            float2 v1 = *reinterpret_cast<float2*>(&acc3[i][1]);
            *(float4*)(out + (size_t)gr * 32 + c4) =
                make_float4(v0.x + bor[0], v0.y + bor[1], v1.x + bor[2], v1.y + bor[3]);
        }
    }
#endif
}

// ---------------- host launcher (multi-stream graph fork/join) ----------------
extern "C" void kernel_launch(void* const* d_in, const int* in_sizes, int n_in,
                              void* d_out, int out_size)
{
    const float* x_host  = (const float*)d_in[0];
    const float* x_flow  = (const float*)d_in[1];
    const int*   src_hf  = (const int*)d_in[2];
    const int*   dst_hf  = (const int*)d_in[3];
    const int*   src_fh  = (const int*)d_in[4];
    const int*   dst_fh  = (const int*)d_in[5];
    const float* W0_hf_l = (const float*)d_in[6];
    const float* W0_hf_r = (const float*)d_in[7];
    const float* b0_hf   = (const float*)d_in[8];
    const float* W0_fh_l = (const float*)d_in[9];
    const float* W0_fh_r = (const float*)d_in[10];
    const float* b0_fh   = (const float*)d_in[11];
    const float* W1_hf_l = (const float*)d_in[12];
    const float* W1_hf_r = (const float*)d_in[13];
    const float* b1_hf   = (const float*)d_in[14];
    // d_in[15..17] unused (g_host discarded)
    const float* W_out   = (const float*)d_in[18];
    const float* b_out   = (const float*)d_in[19];
    float* out = (float*)d_out;

    float *aggX, *cntF, *aggH, *cntH, *th1, *agg2;
    cudaGetSymbolAddress((void**)&aggX, g_aggX);
    cudaGetSymbolAddress((void**)&cntF, g_cntF);
    cudaGetSymbolAddress((void**)&aggH, g_aggH);
    cudaGetSymbolAddress((void**)&cntH, g_cntH);
    cudaGetSymbolAddress((void**)&th1,  g_th1);
    cudaGetSymbolAddress((void**)&agg2, g_agg2);

    cudaFuncSetAttribute(k_host, cudaFuncAttributeMaxDynamicSharedMemorySize, HOST_SMEM_REQ);
    cudaFuncSetAttribute(k_flow_tc, cudaFuncAttributeMaxDynamicSharedMemorySize, FLOW_SMEM_REQ);

    static cudaStream_t s1 = nullptr, s2 = nullptr;
    static cudaEvent_t evFork = nullptr, evFh = nullptr, evHf = nullptr, evA2 = nullptr;
    if (s1 == nullptr) {
        cudaStreamCreateWithFlags(&s1, cudaStreamNonBlocking);
        cudaStreamCreateWithFlags(&s2, cudaStreamNonBlocking);
        cudaEventCreateWithFlags(&evFork, cudaEventDisableTiming);
        cudaEventCreateWithFlags(&evFh, cudaEventDisableTiming);
        cudaEventCreateWithFlags(&evHf, cudaEventDisableTiming);
        cudaEventCreateWithFlags(&evA2, cudaEventDisableTiming);
    }

    // Fork side streams off the origin stream.
    cudaEventRecord(evFork, 0);
    cudaStreamWaitEvent(s1, evFork, 0);
    cudaStreamWaitEvent(s2, evFork, 0);

    // Origin: zero fh-aggregates -> fh-scatter -> host chain (tcgen05)
    k_zero_fh<<<256, 256>>>();
    k_scatter64<<<(NE / 2 + 15) / 16, 256>>>(x_flow, src_fh, dst_fh, aggH, cntH);
    cudaEventRecord(evFh, 0);
    k_host<<<157, 256, HOST_SMEM_REQ>>>(aggH, cntH, x_host,
                                        W0_fh_l, W0_fh_r, b0_fh, W1_hf_l, th1);

    // s1: zero hf-aggregates, then hf-scatter AFTER fh-scatter finishes (runs under k_host)
    k_zero_hf<<<1024, 256, 0, s1>>>();
    cudaStreamWaitEvent(s1, evFh, 0);
    k_scatter64<<<(NE / 2 + 15) / 16, 256, 0, s1>>>(x_host, src_hf, dst_hf, aggX, cntF);
    cudaEventRecord(evHf, s1);

    // s2: zero agg2 (off the critical path)
    k_zero_a2<<<2048, 256, 0, s2>>>();
    cudaEventRecord(evA2, s2);

    // Origin: join agg2-zero, 128-dim scatter, join hf-scatter, flow chain
    cudaStreamWaitEvent(0, evA2, 0);
    k_scatter128<<<(NE / 2 + 7) / 8, 256>>>(th1, src_hf, dst_hf, agg2);
    cudaStreamWaitEvent(0, evHf, 0);
    k_flow_tc<<<148, 256, FLOW_SMEM_REQ>>>(x_flow, aggX, agg2, cntF,
                                           W0_hf_r, W0_hf_l, b0_hf,
                                           W1_hf_r, b1_hf,
                                           W_out, b_out, out);
}

// round 17
// speedup vs baseline: 1.3867x; 1.3867x over previous
#include <cuda_runtime.h>
#include <cuda_bf16.h>
#include <cstdint>

// Problem constants
#define N_HOST 20000
#define N_FLOW 200000
#define NE     600000
#define D_IN   64
#define D_H    128
#define D_OUT  32

#define SC128_GRID 1184

typedef unsigned long long ull;

#if defined(__CUDA_ARCH_FEAT_SM103_ALL) || defined(__CUDA_ARCH_FEAT_SM100_ALL) || defined(__CUDA_ARCH_FEAT_SM101_ALL)
#define HAS_TCGEN05 1
#else
#define HAS_TCGEN05 0
#endif

// ---------------- scratch ----------------
__device__ float g_aggX [(size_t)N_FLOW * D_IN];
__device__ float g_cntF [N_FLOW];
__device__ float g_aggH [(size_t)N_HOST * D_IN];
__device__ float g_cntH [N_HOST];
__device__ float g_th1  [(size_t)N_HOST * D_H];
__device__ float g_agg2 [(size_t)N_FLOW * D_H];
__device__ unsigned g_sc_done;

extern __shared__ char smem_raw[];

// ---------------- generic helpers ----------------
__device__ __forceinline__ float lrelu(float v) { return v > 0.f ? v : 0.01f * v; }

__device__ __forceinline__ uint32_t smem_u32(const void* p) {
    uint32_t a;
    asm("{ .reg .u64 t; cvta.to.shared.u64 t, %1; cvt.u32.u64 %0, t; }" : "=r"(a) : "l"(p));
    return a;
}

__device__ __forceinline__ void wait_sc128_done() {
    unsigned v;
    do {
        asm volatile("ld.acquire.gpu.u32 %0, [%1];" : "=r"(v) : "l"(&g_sc_done) : "memory");
    } while (v < (unsigned)SC128_GRID);
}

// ---------------- f32x2 packed-FMA helpers (fallback path) ----------------
__device__ __forceinline__ ull dup2(float x) {
    ull r; asm("mov.b64 %0, {%1, %1};" : "=l"(r) : "f"(x)); return r;
}
__device__ __forceinline__ void ffma2(ull& acc, ull a, ull b) {
    asm("fma.rn.f32x2 %0, %1, %2, %0;" : "+l"(acc) : "l"(a), "l"(b));
}

template <int K, int AP>
__device__ __forceinline__ void mma_tile(const float* __restrict__ As,
                                         const float* __restrict__ Ws,
                                         int tr8, int tc8, ull acc[8][4])
{
#pragma unroll 4
    for (int kk = 0; kk < K; kk++) {
        const ulonglong2* wp = reinterpret_cast<const ulonglong2*>(Ws + kk * 128 + tc8);
        ulonglong2 w01 = wp[0];
        ulonglong2 w23 = wp[1];
        ull ad[8];
#pragma unroll
        for (int i = 0; i < 8; i++) ad[i] = dup2(As[(tr8 + i) * AP + kk]);
#pragma unroll
        for (int i = 0; i < 8; i++) {
            ffma2(acc[i][0], ad[i], w01.x);
            ffma2(acc[i][1], ad[i], w01.y);
            ffma2(acc[i][2], ad[i], w23.x);
            ffma2(acc[i][3], ad[i], w23.y);
        }
    }
}
__device__ __forceinline__ void zero_acc(ull acc[8][4]) {
#pragma unroll
    for (int i = 0; i < 8; i++)
#pragma unroll
        for (int p = 0; p < 4; p++) acc[i][p] = 0ull;
}

// ---------------- tcgen05 helpers ----------------
#if HAS_TCGEN05
__device__ __forceinline__ bool elect1() {
    uint32_t p;
    asm volatile("{\n\t.reg .pred p;\n\telect.sync _|p, 0xFFFFFFFF;\n\tselp.b32 %0,1,0,p;\n\t}" : "=r"(p));
    return p != 0;
}
__device__ __forceinline__ ull mkdesc(uint32_t addr) {
    return 0x4000404000010000ull | ((ull)(addr >> 4) & 0x3FFFull);
}
__device__ __forceinline__ void mma_ts_f16(uint32_t d, uint32_t a, ull bd, uint32_t idesc, uint32_t acc) {
    asm volatile(
        "{\n\t.reg .pred p;\n\tsetp.ne.u32 p, %5, 0;\n\t"
        "tcgen05.mma.cta_group::1.kind::f16 [%0], [%1], %2, %3, {%4,%4,%4,%4}, p;\n\t}"
        :: "r"(d), "r"(a), "l"(bd), "r"(idesc), "r"(0u), "r"(acc) : "memory");
}
__device__ __forceinline__ void tc_commit(uint32_t mbar) {
    asm volatile("tcgen05.commit.cta_group::1.mbarrier::arrive::one.shared::cluster.b64 [%0];"
                 :: "r"(mbar) : "memory");
}
__device__ __forceinline__ void mbar_init(uint32_t a, uint32_t cnt) {
    asm volatile("mbarrier.init.shared.b64 [%0], %1;" :: "r"(a), "r"(cnt) : "memory");
}
__device__ __forceinline__ void mbar_wait(uint32_t a, uint32_t ph) {
    asm volatile(
        "{\n\t.reg .pred P;\n\tLW%=:\n\t"
        "mbarrier.try_wait.parity.acquire.cta.shared::cta.b64 P, [%0], %1;\n\t"
        "@!P bra LW%=;\n\t}"
        :: "r"(a), "r"(ph) : "memory");
}
#define TC_WAIT_LD()   asm volatile("tcgen05.wait::ld.sync.aligned;" ::: "memory")
#define TC_WAIT_ST()   asm volatile("tcgen05.wait::st.sync.aligned;" ::: "memory")
#define TC_FENCE_B()   asm volatile("tcgen05.fence::before_thread_sync;" ::: "memory")
#define TC_FENCE_A()   asm volatile("tcgen05.fence::after_thread_sync;" ::: "memory")
#define FENCE_PROXY()  asm volatile("fence.proxy.async.shared::cta;" ::: "memory")

__device__ __forceinline__ void ldtm32(uint32_t* r, uint32_t a) {
    asm volatile(
        "tcgen05.ld.sync.aligned.32x32b.x32.b32 "
        "{%0,%1,%2,%3,%4,%5,%6,%7,%8,%9,%10,%11,%12,%13,%14,%15,"
        "%16,%17,%18,%19,%20,%21,%22,%23,%24,%25,%26,%27,%28,%29,%30,%31}, [%32];"
        : "=r"(r[0]), "=r"(r[1]), "=r"(r[2]), "=r"(r[3]), "=r"(r[4]), "=r"(r[5]), "=r"(r[6]), "=r"(r[7]),
          "=r"(r[8]), "=r"(r[9]), "=r"(r[10]), "=r"(r[11]), "=r"(r[12]), "=r"(r[13]), "=r"(r[14]), "=r"(r[15]),
          "=r"(r[16]), "=r"(r[17]), "=r"(r[18]), "=r"(r[19]), "=r"(r[20]), "=r"(r[21]), "=r"(r[22]), "=r"(r[23]),
          "=r"(r[24]), "=r"(r[25]), "=r"(r[26]), "=r"(r[27]), "=r"(r[28]), "=r"(r[29]), "=r"(r[30]), "=r"(r[31])
        : "r"(a));
}
__device__ __forceinline__ void sttm_x8(uint32_t a, const uint32_t* r) {
    asm volatile(
        "tcgen05.st.sync.aligned.32x32b.x8.b32 [%0], {%1,%2,%3,%4,%5,%6,%7,%8};"
        :: "r"(a), "r"(r[0]), "r"(r[1]), "r"(r[2]), "r"(r[3]),
           "r"(r[4]), "r"(r[5]), "r"(r[6]), "r"(r[7]) : "memory");
}
__device__ __forceinline__ void sttm_x16(uint32_t a, const uint32_t* r) {
    asm volatile(
        "tcgen05.st.sync.aligned.32x32b.x16.b32 [%0], "
        "{%1,%2,%3,%4,%5,%6,%7,%8,%9,%10,%11,%12,%13,%14,%15,%16};"
        :: "r"(a), "r"(r[0]), "r"(r[1]), "r"(r[2]), "r"(r[3]),
           "r"(r[4]), "r"(r[5]), "r"(r[6]), "r"(r[7]),
           "r"(r[8]), "r"(r[9]), "r"(r[10]), "r"(r[11]),
           "r"(r[12]), "r"(r[13]), "r"(r[14]), "r"(r[15]) : "memory");
}

__device__ __forceinline__ uint32_t swz_bf16(int row, int col, int nar) {
    uint32_t b = (uint32_t)((row >> 3) + (col >> 6) * nar) * 1024u
               + (uint32_t)(row & 7) * 128u + (uint32_t)(col & 63) * 2u;
    return b ^ ((b >> 3) & 0x70u);
}

__device__ __forceinline__ void pack_hilo(float v0, float v1, uint32_t& h, uint32_t& l) {
    asm("cvt.rn.bf16x2.f32 %0, %1, %2;" : "=r"(h) : "f"(v1), "f"(v0));
    float h0 = __uint_as_float(h << 16);
    float h1 = __uint_as_float(h & 0xffff0000u);
    asm("cvt.rn.bf16x2.f32 %0, %1, %2;" : "=r"(l) : "f"(v1 - h1), "f"(v0 - h0));
}
#endif  // HAS_TCGEN05

// ---------------- zero kernels ----------------
__global__ void k_zero_fh() {
    size_t i = (size_t)blockIdx.x * blockDim.x + threadIdx.x;
    size_t stride = (size_t)gridDim.x * blockDim.x;
    const float4 z = make_float4(0.f, 0.f, 0.f, 0.f);
    for (size_t k = i; k < ((size_t)N_HOST * D_IN) / 4; k += stride) ((float4*)g_aggH)[k] = z;
    for (size_t k = i; k < (size_t)N_HOST / 4; k += stride) ((float4*)g_cntH)[k] = z;
}
__global__ void k_zero_hf() {
    size_t i = (size_t)blockIdx.x * blockDim.x + threadIdx.x;
    size_t stride = (size_t)gridDim.x * blockDim.x;
    const float4 z = make_float4(0.f, 0.f, 0.f, 0.f);
    for (size_t k = i; k < ((size_t)N_FLOW * D_IN) / 4; k += stride) ((float4*)g_aggX)[k] = z;
    for (size_t k = i; k < (size_t)N_FLOW / 4; k += stride) ((float4*)g_cntF)[k] = z;
}
__global__ void k_zero_a2() {
    if (blockIdx.x == 0 && threadIdx.x == 0) g_sc_done = 0u;   // reset sc128 completion counter
    size_t i = (size_t)blockIdx.x * blockDim.x + threadIdx.x;
    size_t stride = (size_t)gridDim.x * blockDim.x;
    const float4 z = make_float4(0.f, 0.f, 0.f, 0.f);
    for (size_t k = i; k < ((size_t)N_FLOW * D_H) / 4; k += stride) ((float4*)g_agg2)[k] = z;
}

// ---------------- 64-dim edge scatter (single edge per lane-group; proven) ----------------
__global__ __launch_bounds__(256) void k_scatter64(
    const float* __restrict__ feat, const int* __restrict__ src,
    const int* __restrict__ dst, float* __restrict__ agg, float* __restrict__ cnt)
{
    int eloc = threadIdx.x >> 4;
    int lane = threadIdx.x & 15;
    int e = blockIdx.x * 16 + eloc;
    if (e >= NE) return;
    int s = __ldg(src + e);
    int d = __ldg(dst + e);
    float4 v = *(const float4*)(feat + (size_t)s * 64 + lane * 4);
    float* p = agg + (size_t)d * 64 + lane * 4;
    asm volatile("red.global.add.v4.f32 [%0], {%1,%2,%3,%4};"
                 :: "l"(p), "f"(v.x), "f"(v.y), "f"(v.z), "f"(v.w) : "memory");
    if (lane == 0) atomicAdd(cnt + d, 1.0f);
}

// ---------------- 128-dim scatter (grid-stride + completion counter) ----------------
__global__ __launch_bounds__(256) void k_scatter128(
    const float* __restrict__ feat, const int* __restrict__ src,
    const int* __restrict__ dst, float* __restrict__ agg)
{
    int eloc = threadIdx.x >> 5;
    int lane = threadIdx.x & 31;
    for (int e = blockIdx.x * 8 + eloc; e < NE; e += gridDim.x * 8) {
        int s = __ldg(src + e);
        int d = __ldg(dst + e);
        float4 v = *(const float4*)(feat + (size_t)s * 128 + lane * 4);
        float* p = agg + (size_t)d * 128 + lane * 4;
        asm volatile("red.global.add.v4.f32 [%0], {%1,%2,%3,%4};"
                     :: "l"(p), "f"(v.x), "f"(v.y), "f"(v.z), "f"(v.w) : "memory");
    }
    __threadfence();
    __syncthreads();
    if (threadIdx.x == 0) atomicAdd(&g_sc_done, 1u);
}

// ================= host chain: th1 = lrelu([aggH*inv|xh]@[W0l;W0r]+b0) @ W1l =================
struct HostSmem {            // FFMA2 fallback layout (also bounds the smem request)
    float Ws0[128 * 128];
    float Ws1[128 * 128];
    float Buf[128 * 132];
};
#define HOST_SMEM_REQ ((int)sizeof(HostSmem))

__global__ __launch_bounds__(256, 1) void k_host(
    const float* __restrict__ aggH, const float* __restrict__ cntH,
    const float* __restrict__ xh,
    const float* __restrict__ W0l, const float* __restrict__ W0r,
    const float* __restrict__ b0,
    const float* __restrict__ W1l,
    float* __restrict__ th1)
{
#if HAS_TCGEN05
    const int tid = threadIdx.x;
    const int wid = tid >> 5;
    const int lane = tid & 31;

    uint32_t raw = smem_u32(smem_raw);
    uint32_t base = (raw + 1023u) & ~1023u;
    char* sp = smem_raw + (base - raw);
    char* pW0H = sp;          char* pW0L = sp + 32768;
    char* pW1H = sp + 65536;  char* pW1L = sp + 98304;
    float* b0s = (float*)(sp + 131072);
    const uint32_t MB = base + 131584;
    const uint32_t TP = base + 131600;

    for (int i = tid; i < 128 * 128; i += 256) {
        int k = i >> 7, n = i & 127;
        float v = (k < 64) ? W0l[k * 128 + n] : W0r[(k - 64) * 128 + n];
        __nv_bfloat16 h = __float2bfloat16(v);
        __nv_bfloat16 l = __float2bfloat16(v - __bfloat162float(h));
        uint32_t o = swz_bf16(n, k, 16);
        *(__nv_bfloat16*)(pW0H + o) = h;
        *(__nv_bfloat16*)(pW0L + o) = l;
    }
    for (int i = tid; i < 128 * 128; i += 256) {
        int k = i >> 7, n = i & 127;
        float v = W1l[i];
        __nv_bfloat16 h = __float2bfloat16(v);
        __nv_bfloat16 l = __float2bfloat16(v - __bfloat162float(h));
        uint32_t o = swz_bf16(n, k, 16);
        *(__nv_bfloat16*)(pW1H + o) = h;
        *(__nv_bfloat16*)(pW1L + o) = l;
    }
    for (int i = tid; i < 128; i += 256) b0s[i] = b0[i];
    if (tid == 0) { mbar_init(MB, 1); mbar_init(MB + 8, 1); }
    if (wid == 0) {
        asm volatile("tcgen05.alloc.cta_group::1.sync.aligned.shared::cta.b32 [%0], %1;"
                     :: "r"(TP), "r"(256) : "memory");
        asm volatile("tcgen05.relinquish_alloc_permit.cta_group::1.sync.aligned;");
    }
    FENCE_PROXY();
    __syncthreads();
    uint32_t tmem;
    asm volatile("ld.shared.b32 %0, [%1];" : "=r"(tmem) : "r"(TP));

    const ull d0H = mkdesc(base), d0L = mkdesc(base + 32768);
    const ull d1H = mkdesc(base + 65536), d1L = mkdesc(base + 98304);
    const uint32_t idesc128 = 0x8200490u;
    const int BOW[8] = {0, 2, 4, 6, 1024, 1026, 1028, 1030};

    const int sub = wid & 3, half = wid >> 2;
    const int r = sub * 32 + lane;
    const uint32_t tm_row = (uint32_t)sub << 21;
    const int c0a = half * 32, c0b = 64 + half * 32;
    const uint32_t SA = tmem, SD = tmem + 128;

    const int NT = (N_HOST + 127) >> 7;    // 157
    int it = 0;
    for (int tile = blockIdx.x; tile < NT; tile += gridDim.x, ++it) {
        const int row0 = tile << 7;
        const int ge = row0 + r;
        const int gs = ge < N_HOST ? ge : N_HOST - 1;
        const int par = it & 1;

        float inv = 1.f / fmaxf(__ldg(cntH + gs), 1.f);
        {
            const float* src = half ? (xh + (size_t)gs * 64) : (aggH + (size_t)gs * 64);
            float sc = half ? 1.f : inv;
            uint32_t A0 = SA + (uint32_t)(half * 32) + tm_row;
#pragma unroll
            for (int q = 0; q < 4; q++) {
                const float4* p4 = (const float4*)(src + q * 16);
                float4 f0 = p4[0], f1 = p4[1], f2 = p4[2], f3 = p4[3];
                float e[16] = {f0.x, f0.y, f0.z, f0.w, f1.x, f1.y, f1.z, f1.w,
                               f2.x, f2.y, f2.z, f2.w, f3.x, f3.y, f3.z, f3.w};
                uint32_t hi[8], lo[8];
#pragma unroll
                for (int i = 0; i < 8; i++) pack_hilo(e[2 * i] * sc, e[2 * i + 1] * sc, hi[i], lo[i]);
                sttm_x8(A0 + q * 8, hi);
                sttm_x8(A0 + 64 + q * 8, lo);
            }
            TC_WAIT_ST();
        }
        TC_FENCE_B();
        __syncthreads();

        if (wid == 0) {
            TC_FENCE_A();
            if (elect1()) {
#pragma unroll
                for (int s = 0; s < 8; s++) mma_ts_f16(SD, SA + s * 8, d0H + BOW[s], idesc128, s > 0);
#pragma unroll
                for (int s = 0; s < 8; s++) mma_ts_f16(SD, SA + s * 8, d0L + BOW[s], idesc128, 1);
#pragma unroll
                for (int s = 0; s < 8; s++) mma_ts_f16(SD, SA + 64 + s * 8, d0H + BOW[s], idesc128, 1);
                tc_commit(MB);
            }
        }
        mbar_wait(MB, par);
        TC_FENCE_A();

        {
            uint32_t dr[32], hi[16], lo[16];
            ldtm32(dr, SD + c0a + tm_row);
            TC_WAIT_LD();
#pragma unroll
            for (int j = 0; j < 32; j += 2) {
                float v0 = lrelu(__uint_as_float(dr[j])     + b0s[c0a + j]);
                float v1 = lrelu(__uint_as_float(dr[j + 1]) + b0s[c0a + j + 1]);
                pack_hilo(v0, v1, hi[j >> 1], lo[j >> 1]);
            }
            sttm_x16(SA + (c0a >> 1) + tm_row, hi);
            sttm_x16(SA + 64 + (c0a >> 1) + tm_row, lo);
            ldtm32(dr, SD + c0b + tm_row);
            TC_WAIT_LD();
#pragma unroll
            for (int j = 0; j < 32; j += 2) {
                float v0 = lrelu(__uint_as_float(dr[j])     + b0s[c0b + j]);
                float v1 = lrelu(__uint_as_float(dr[j + 1]) + b0s[c0b + j + 1]);
                pack_hilo(v0, v1, hi[j >> 1], lo[j >> 1]);
            }
            sttm_x16(SA + (c0b >> 1) + tm_row, hi);
            sttm_x16(SA + 64 + (c0b >> 1) + tm_row, lo);
            TC_WAIT_ST();
        }
        TC_FENCE_B();
        __syncthreads();

        if (wid == 0) {
            TC_FENCE_A();
            if (elect1()) {
#pragma unroll
                for (int s = 0; s < 8; s++) mma_ts_f16(SD, SA + s * 8, d1H + BOW[s], idesc128, s > 0);
#pragma unroll
                for (int s = 0; s < 8; s++) mma_ts_f16(SD, SA + s * 8, d1L + BOW[s], idesc128, 1);
#pragma unroll
                for (int s = 0; s < 8; s++) mma_ts_f16(SD, SA + 64 + s * 8, d1H + BOW[s], idesc128, 1);
                tc_commit(MB + 8);
            }
        }
        mbar_wait(MB + 8, par);
        TC_FENCE_A();

        {
            uint32_t dr[32];
            ldtm32(dr, SD + c0a + tm_row);
            TC_WAIT_LD();
            if (ge < N_HOST) {
                float* tp = th1 + (size_t)ge * 128 + c0a;
#pragma unroll
                for (int j = 0; j < 32; j += 4)
                    *(float4*)(tp + j) = make_float4(
                        __uint_as_float(dr[j]), __uint_as_float(dr[j + 1]),
                        __uint_as_float(dr[j + 2]), __uint_as_float(dr[j + 3]));
            }
            ldtm32(dr, SD + c0b + tm_row);
            TC_WAIT_LD();
            if (ge < N_HOST) {
                float* tp = th1 + (size_t)ge * 128 + c0b;
#pragma unroll
                for (int j = 0; j < 32; j += 4)
                    *(float4*)(tp + j) = make_float4(
                        __uint_as_float(dr[j]), __uint_as_float(dr[j + 1]),
                        __uint_as_float(dr[j + 2]), __uint_as_float(dr[j + 3]));
            }
        }
        TC_FENCE_B();
    }

    __syncthreads();
    if (wid == 0) {
        asm volatile("tcgen05.dealloc.cta_group::1.sync.aligned.b32 %0, %1;" :: "r"(tmem), "r"(256));
    }
#else
    HostSmem* S = reinterpret_cast<HostSmem*>(smem_raw);
    const int tid = threadIdx.x;
    for (int i = tid; i < 128 * 128; i += 256) {
        int k = i >> 7, n = i & 127;
        S->Ws0[i] = (k < 64) ? W0l[k * 128 + n] : W0r[(k - 64) * 128 + n];
    }
    for (int f = tid; f < 128 * 128 / 4; f += 256) ((float4*)S->Ws1)[f] = ((const float4*)W1l)[f];

    const int tr8 = (tid >> 4) * 8;
    const int tc8 = (tid & 15) * 8;
    float b0r[8];
#pragma unroll
    for (int j = 0; j < 8; j++) b0r[j] = b0[tc8 + j];

    const int NT = (N_HOST + 127) / 128;
    for (int tile = blockIdx.x; tile < NT; tile += gridDim.x) {
        const int row0 = tile * 128;
        __syncthreads();
        for (int f = tid; f < 4096; f += 256) {
            int r = f >> 5, cc = (f & 31) * 4;
            int gr = row0 + r;
            if (gr >= N_HOST) continue;
            float4 v;
            if (cc < 64) {
                float inv = 1.f / fmaxf(__ldg(cntH + gr), 1.f);
                v = *(const float4*)(aggH + (size_t)gr * 64 + cc);
                v.x *= inv; v.y *= inv; v.z *= inv; v.w *= inv;
            } else {
                v = *(const float4*)(xh + (size_t)gr * 64 + (cc - 64));
            }
            *(float4*)(&S->Buf[r * 132 + cc]) = v;
        }
        __syncthreads();

        ull acc[8][4];
        zero_acc(acc);
        mma_tile<128, 132>(S->Buf, S->Ws0, tr8, tc8, acc);
        __syncthreads();
#pragma unroll
        for (int i = 0; i < 8; i++) {
#pragma unroll
            for (int p = 0; p < 4; p++) {
                float2 v = *reinterpret_cast<float2*>(&acc[i][p]);
                S->Buf[(tr8 + i) * 132 + tc8 + 2 * p]     = lrelu(v.x + b0r[2 * p]);
                S->Buf[(tr8 + i) * 132 + tc8 + 2 * p + 1] = lrelu(v.y + b0r[2 * p + 1]);
            }
        }
        __syncthreads();

        zero_acc(acc);
        mma_tile<128, 132>(S->Buf, S->Ws1, tr8, tc8, acc);
#pragma unroll
        for (int i = 0; i < 8; i++) {
            int gr = row0 + tr8 + i;
            if (gr >= N_HOST) continue;
            float2 v0 = *reinterpret_cast<float2*>(&acc[i][0]);
            float2 v1 = *reinterpret_cast<float2*>(&acc[i][1]);
            float2 v2 = *reinterpret_cast<float2*>(&acc[i][2]);
            float2 v3 = *reinterpret_cast<float2*>(&acc[i][3]);
            *(float4*)(th1 + (size_t)gr * 128 + tc8)     = make_float4(v0.x, v0.y, v1.x, v1.y);
            *(float4*)(th1 + (size_t)gr * 128 + tc8 + 4) = make_float4(v2.x, v2.y, v3.x, v3.y);
        }
    }
#endif
}

// ================= flow chain (paired-tile tcgen05 pipeline, balanced tile ranges) =================
#define O_W01H 0
#define O_W01L 32768
#define O_W1H  65536
#define O_W1L  98304
#define O_WOH  131072
#define O_WOL  139264
#define O_B0   147456
#define O_B1   147968
#define O_BO   148480
#define O_MB   148608
#define O_TP   148656
#define TM_SA0 0
#define TM_SA1 128
#define TM_SD0 256
#define TM_SD1 384

#define FLOW_SMEM_REQ 231936

__global__ __launch_bounds__(256, 1)
void k_flow_tc(const float* __restrict__ xf,
               const float* __restrict__ aggX, const float* __restrict__ agg2,
               const float* __restrict__ cnt,
               const float* __restrict__ W0r, const float* __restrict__ W0l,
               const float* __restrict__ b0,
               const float* __restrict__ W1r, const float* __restrict__ b1,
               const float* __restrict__ Wo,  const float* __restrict__ bo,
               float* __restrict__ out)
{
#if HAS_TCGEN05
    const int tid = threadIdx.x;
    const int wid = tid >> 5;
    const int lane = tid & 31;

    uint32_t raw = smem_u32(smem_raw);
    uint32_t base = (raw + 1023u) & ~1023u;
    char* sp = smem_raw + (base - raw);

    char* pW01H = sp + O_W01H; char* pW01L = sp + O_W01L;
    char* pW1H  = sp + O_W1H;  char* pW1L  = sp + O_W1L;
    char* pWOH  = sp + O_WOH;  char* pWOL  = sp + O_WOL;
    float* b0s = (float*)(sp + O_B0);
    float* b1s = (float*)(sp + O_B1);
    float* bos = (float*)(sp + O_BO);
    const uint32_t MB = base + O_MB;

    for (int i = tid; i < 128 * 128; i += 256) {
        int k = i >> 7, n = i & 127;
        float v = (k < 64) ? W0r[k * 128 + n] : W0l[(k - 64) * 128 + n];
        __nv_bfloat16 h = __float2bfloat16(v);
        __nv_bfloat16 l = __float2bfloat16(v - __bfloat162float(h));
        uint32_t o = swz_bf16(n, k, 16);
        *(__nv_bfloat16*)(pW01H + o) = h;
        *(__nv_bfloat16*)(pW01L + o) = l;
    }
    for (int i = tid; i < 128 * 128; i += 256) {
        int k = i >> 7, n = i & 127;
        float v = W1r[i];
        __nv_bfloat16 h = __float2bfloat16(v);
        __nv_bfloat16 l = __float2bfloat16(v - __bfloat162float(h));
        uint32_t o = swz_bf16(n, k, 16);
        *(__nv_bfloat16*)(pW1H + o) = h;
        *(__nv_bfloat16*)(pW1L + o) = l;
    }
    for (int i = tid; i < 128 * 32; i += 256) {
        int k = i >> 5, n = i & 31;
        float v = Wo[i];
        __nv_bfloat16 h = __float2bfloat16(v);
        __nv_bfloat16 l = __float2bfloat16(v - __bfloat162float(h));
        uint32_t o = swz_bf16(n, k, 4);
        *(__nv_bfloat16*)(pWOH + o) = h;
        *(__nv_bfloat16*)(pWOL + o) = l;
    }
    for (int i = tid; i < 128; i += 256) { b0s[i] = b0[i]; b1s[i] = b1[i]; }
    if (tid < 32) bos[tid] = bo[tid];
    if (tid == 0) {
#pragma unroll
        for (int m = 0; m < 6; m++) mbar_init(MB + 8 * m, 1);
    }
    if (wid == 0) {
        asm volatile("tcgen05.alloc.cta_group::1.sync.aligned.shared::cta.b32 [%0], %1;"
                     :: "r"(base + O_TP), "r"(512) : "memory");
    }
    FENCE_PROXY();
    __syncthreads();
    uint32_t tmem;
    asm volatile("ld.shared.b32 %0, [%1];" : "=r"(tmem) : "r"(base + O_TP));

    const ull d0H = mkdesc(base + O_W01H), d0L = mkdesc(base + O_W01L);
    const ull d1H = mkdesc(base + O_W1H),  d1L = mkdesc(base + O_W1L);
    const ull dOH = mkdesc(base + O_WOH),  dOL = mkdesc(base + O_WOL);
    const uint32_t idesc128 = 0x8200490u;
    const uint32_t idesc32  = 0x8080490u;

    const int sub = wid & 3, half = wid >> 2;
    const int r = sub * 32 + lane;
    const uint32_t tm_row = (uint32_t)sub << 21;
    const int c0a = half * 32;
    const int c0b = 64 + half * 32;

    const uint32_t SA0 = tmem + TM_SA0, SA1 = tmem + TM_SA1;
    const uint32_t SD0 = tmem + TM_SD0, SD1 = tmem + TM_SD1;

    const int NT = (N_FLOW + 127) >> 7;    // 1563

    const int BOW[8] = {0, 2, 4, 6, 1024, 1026, 1028, 1030};
    const int BOO[8] = {0, 2, 4, 6, 256, 258, 260, 262};

    auto load_A = [&](int row0n, uint32_t slot) -> float {
        int gn = row0n + r;
        int gs = gn < N_FLOW ? gn : N_FLOW - 1;
        float inv = 1.f / fmaxf(__ldg(cnt + gs), 1.f);
        const float* src = half ? (aggX + (size_t)gs * 64) : (xf + (size_t)gs * 64);
        float sc = half ? inv : 1.f;
        uint32_t A0 = slot + (uint32_t)(half * 32) + tm_row;
#pragma unroll
        for (int q = 0; q < 4; q++) {
            const float4* p4 = (const float4*)(src + q * 16);
            float4 f0 = p4[0], f1 = p4[1], f2 = p4[2], f3 = p4[3];
            float e[16] = {f0.x, f0.y, f0.z, f0.w, f1.x, f1.y, f1.z, f1.w,
                           f2.x, f2.y, f2.z, f2.w, f3.x, f3.y, f3.z, f3.w};
            uint32_t hi[8], lo[8];
#pragma unroll
            for (int i = 0; i < 8; i++) pack_hilo(e[2 * i] * sc, e[2 * i + 1] * sc, hi[i], lo[i]);
            sttm_x8(A0 + q * 8, hi);
            sttm_x8(A0 + 64 + q * 8, lo);
        }
        TC_WAIT_ST();
        return inv;
    };

    auto mma_phase = [&](uint32_t a0, uint32_t dD, ull bh, ull bl, const int* BO, uint32_t idesc) {
#pragma unroll
        for (int s = 0; s < 8; s++) mma_ts_f16(dD, a0 + s * 8, bh + BO[s], idesc, s > 0);
#pragma unroll
        for (int s = 0; s < 8; s++) mma_ts_f16(dD, a0 + s * 8, bl + BO[s], idesc, 1);
#pragma unroll
        for (int s = 0; s < 8; s++) mma_ts_f16(dD, a0 + 64 + s * 8, bh + BO[s], idesc, 1);
    };

    auto epi1 = [&](uint32_t dSlot, uint32_t aSlot) {
        uint32_t dr[32], hi[16], lo[16];
        ldtm32(dr, dSlot + c0a + tm_row);
        TC_WAIT_LD();
#pragma unroll
        for (int j = 0; j < 32; j += 2) {
            float v0 = lrelu(__uint_as_float(dr[j])     + b0s[c0a + j]);
            float v1 = lrelu(__uint_as_float(dr[j + 1]) + b0s[c0a + j + 1]);
            pack_hilo(v0, v1, hi[j >> 1], lo[j >> 1]);
        }
        sttm_x16(aSlot + (c0a >> 1) + tm_row, hi);
        sttm_x16(aSlot + 64 + (c0a >> 1) + tm_row, lo);
        ldtm32(dr, dSlot + c0b + tm_row);
        TC_WAIT_LD();
#pragma unroll
        for (int j = 0; j < 32; j += 2) {
            float v0 = lrelu(__uint_as_float(dr[j])     + b0s[c0b + j]);
            float v1 = lrelu(__uint_as_float(dr[j + 1]) + b0s[c0b + j + 1]);
            pack_hilo(v0, v1, hi[j >> 1], lo[j >> 1]);
        }
        sttm_x16(aSlot + (c0b >> 1) + tm_row, hi);
        sttm_x16(aSlot + 64 + (c0b >> 1) + tm_row, lo);
        TC_WAIT_ST();
    };

    auto prefetch2 = [&](int ge, float4* q0, float4* q1) {
        int gs = ge < N_FLOW ? ge : N_FLOW - 1;
        const float4* ap = (const float4*)(agg2 + (size_t)gs * 128);
#pragma unroll
        for (int i = 0; i < 8; i++) q0[i] = ap[(c0a >> 2) + i];
#pragma unroll
        for (int i = 0; i < 8; i++) q1[i] = ap[(c0b >> 2) + i];
    };

    auto epi2 = [&](uint32_t dSlot, uint32_t aSlot, const float4* q0, const float4* q1, float inv) {
        uint32_t dr[32], hi[16], lo[16];
        ldtm32(dr, dSlot + c0a + tm_row);
        TC_WAIT_LD();
#pragma unroll
        for (int j = 0; j < 32; j += 4) {
            float4 av = q0[j >> 2];
            float v0 = lrelu(__uint_as_float(dr[j])     + av.x * inv + b1s[c0a + j]);
            float v1 = lrelu(__uint_as_float(dr[j + 1]) + av.y * inv + b1s[c0a + j + 1]);
            float v2 = lrelu(__uint_as_float(dr[j + 2]) + av.z * inv + b1s[c0a + j + 2]);
            float v3 = lrelu(__uint_as_float(dr[j + 3]) + av.w * inv + b1s[c0a + j + 3]);
            pack_hilo(v0, v1, hi[j >> 1], lo[j >> 1]);
            pack_hilo(v2, v3, hi[(j >> 1) + 1], lo[(j >> 1) + 1]);
        }
        sttm_x16(aSlot + (c0a >> 1) + tm_row, hi);
        sttm_x16(aSlot + 64 + (c0a >> 1) + tm_row, lo);
        ldtm32(dr, dSlot + c0b + tm_row);
        TC_WAIT_LD();
#pragma unroll
        for (int j = 0; j < 32; j += 4) {
            float4 av = q1[j >> 2];
            float v0 = lrelu(__uint_as_float(dr[j])     + av.x * inv + b1s[c0b + j]);
            float v1 = lrelu(__uint_as_float(dr[j + 1]) + av.y * inv + b1s[c0b + j + 1]);
            float v2 = lrelu(__uint_as_float(dr[j + 2]) + av.z * inv + b1s[c0b + j + 2]);
            float v3 = lrelu(__uint_as_float(dr[j + 3]) + av.w * inv + b1s[c0b + j + 3]);
            pack_hilo(v0, v1, hi[j >> 1], lo[j >> 1]);
            pack_hilo(v2, v3, hi[(j >> 1) + 1], lo[(j >> 1) + 1]);
        }
        sttm_x16(aSlot + (c0b >> 1) + tm_row, hi);
        sttm_x16(aSlot + 64 + (c0b >> 1) + tm_row, lo);
        TC_WAIT_ST();
    };

    auto epi3 = [&](uint32_t dSlot, int ge) {
        if (wid >= 4) return;
        uint32_t dr[32];
        ldtm32(dr, dSlot + tm_row);
        TC_WAIT_LD();
        if (ge < N_FLOW) {
            float* op = out + (size_t)ge * 32;
#pragma unroll
            for (int c = 0; c < 32; c += 4) {
                *(float4*)(op + c) = make_float4(
                    __uint_as_float(dr[c])     + bos[c],
                    __uint_as_float(dr[c + 1]) + bos[c + 1],
                    __uint_as_float(dr[c + 2]) + bos[c + 2],
                    __uint_as_float(dr[c + 3]) + bos[c + 3]);
            }
        }
    };

    // balanced contiguous tile ranges: max 11 tiles/CTA (vs 12 with pair-striding)
    const int qt = NT / (int)gridDim.x;
    const int remt = NT - qt * (int)gridDim.x;
    const int myN = qt + ((int)blockIdx.x < remt ? 1 : 0);
    const int myStart = (int)blockIdx.x * qt + min((int)blockIdx.x, remt);

    bool a2ready = false;
    int it = 0;
    for (int i = 0; i < myN; i += 2, ++it) {
        const int tileA = myStart + i, tileB = tileA + 1;
        const bool vB = (i + 1) < myN;
        const int row0A = tileA << 7, row0B = tileB << 7;
        const int geA = row0A + r, geB = row0B + r;
        const int par = it & 1;
        __syncthreads();

        float invA = load_A(row0A, SA0);
        float invB = 1.f;
        if (vB) invB = load_A(row0B, SA1);
        TC_FENCE_B();
        __syncthreads();

        if (wid == 0) {
            TC_FENCE_A();
            if (elect1()) {
                mma_phase(SA0, SD0, d0H, d0L, BOW, idesc128); tc_commit(MB + 0);
                if (vB) { mma_phase(SA1, SD1, d0H, d0L, BOW, idesc128); tc_commit(MB + 8); }
            }
        }

        mbar_wait(MB + 0, par); TC_FENCE_A();
        epi1(SD0, SA0);
        TC_FENCE_B(); __syncthreads();
        if (wid == 0) {
            TC_FENCE_A();
            if (elect1()) { mma_phase(SA0, SD0, d1H, d1L, BOW, idesc128); tc_commit(MB + 16); }
        }

        // gate: agg2 must be fully scattered before first agg2 read
        if (!a2ready) {
            if (tid == 0) wait_sc128_done();
            __syncthreads();
            a2ready = true;
        }
        float4 qa0[8], qa1[8];
        prefetch2(geA, qa0, qa1);

        if (vB) {
            mbar_wait(MB + 8, par); TC_FENCE_A();
            epi1(SD1, SA1);
            TC_FENCE_B(); __syncthreads();
            if (wid == 0) {
                TC_FENCE_A();
                if (elect1()) { mma_phase(SA1, SD1, d1H, d1L, BOW, idesc128); tc_commit(MB + 24); }
            }
        }

        mbar_wait(MB + 16, par); TC_FENCE_A();
        epi2(SD0, SA0, qa0, qa1, invA);
        TC_FENCE_B(); __syncthreads();
        if (wid == 0) {
            TC_FENCE_A();
            if (elect1()) { mma_phase(SA0, SD0, dOH, dOL, BOO, idesc32); tc_commit(MB + 32); }
        }

        if (vB) {
            float4 qb0[8], qb1[8];
            prefetch2(geB, qb0, qb1);
            mbar_wait(MB + 24, par); TC_FENCE_A();
            epi2(SD1, SA1, qb0, qb1, invB);
            TC_FENCE_B(); __syncthreads();
            if (wid == 0) {
                TC_FENCE_A();
                if (elect1()) { mma_phase(SA1, SD1, dOH, dOL, BOO, idesc32); tc_commit(MB + 40); }
            }
        }

        mbar_wait(MB + 32, par); TC_FENCE_A();
        epi3(SD0, geA);
        if (vB) {
            mbar_wait(MB + 40, par); TC_FENCE_A();
            epi3(SD1, geB);
        }
        TC_FENCE_B();
    }

    __syncthreads();
    if (wid == 0) {
        asm volatile("tcgen05.relinquish_alloc_permit.cta_group::1.sync.aligned;");
        asm volatile("tcgen05.dealloc.cta_group::1.sync.aligned.b32 %0, %1;" :: "r"(tmem), "r"(512));
    }
#else
    // ==================== FFMA2 fallback path ====================
    if (threadIdx.x == 0) wait_sc128_done();
    __syncthreads();

    float* Ws0a = (float*)smem_raw;
    float* Ws0b = Ws0a + 64 * 128;
    float* Ws1  = Ws0b + 64 * 128;
    float* Asf  = Ws1 + 128 * 128;
    float* H    = Asf + 128 * 68;

    const int tid = threadIdx.x;
    for (int f = tid; f < 64 * 128 / 4; f += 256) {
        ((float4*)Ws0a)[f] = ((const float4*)W0r)[f];
        ((float4*)Ws0b)[f] = ((const float4*)W0l)[f];
    }
    for (int f = tid; f < 128 * 128 / 4; f += 256) ((float4*)Ws1)[f] = ((const float4*)W1r)[f];

    const int tr8 = (tid >> 4) * 8;
    const int tc8 = (tid & 15) * 8;
    float b0r[8], b1r[8];
#pragma unroll
    for (int j = 0; j < 8; j++) { b0r[j] = b0[tc8 + j]; b1r[j] = b1[tc8 + j]; }
    const int r4 = (tid >> 3) * 4;
    const int c4 = (tid & 7) * 4;
    float bor[4];
#pragma unroll
    for (int j = 0; j < 4; j++) bor[j] = bo[c4 + j];

    const int NT = (N_FLOW + 127) / 128;
    for (int tile = blockIdx.x; tile < NT; tile += gridDim.x) {
        const int row0 = tile * 128;
        __syncthreads();
        for (int f = tid; f < 2048; f += 256) {
            int r = f >> 4, cc = (f & 15) * 4;
            int gr = row0 + r;
            if (gr < N_FLOW)
                *(float4*)(Asf + r * 68 + cc) = *(const float4*)(xf + (size_t)gr * 64 + cc);
        }
        __syncthreads();

        ull acc[8][4];
        zero_acc(acc);
        mma_tile<64, 68>(Asf, Ws0a, tr8, tc8, acc);
        __syncthreads();
        for (int f = tid; f < 2048; f += 256) {
            int r = f >> 4, cc = (f & 15) * 4;
            int gr = row0 + r;
            if (gr < N_FLOW) {
                float inv = 1.f / fmaxf(__ldg(cnt + gr), 1.f);
                float4 v = *(const float4*)(aggX + (size_t)gr * 64 + cc);
                v.x *= inv; v.y *= inv; v.z *= inv; v.w *= inv;
                *(float4*)(Asf + r * 68 + cc) = v;
            }
        }
        __syncthreads();
        mma_tile<64, 68>(Asf, Ws0b, tr8, tc8, acc);

#pragma unroll
        for (int i = 0; i < 8; i++) {
            int gr = row0 + tr8 + i;
            if (gr >= N_FLOW) continue;
#pragma unroll
            for (int p = 0; p < 4; p++) {
                float2 v = *reinterpret_cast<float2*>(&acc[i][p]);
                H[(tr8 + i) * 129 + tc8 + 2 * p]     = lrelu(v.x + b0r[2 * p]);
                H[(tr8 + i) * 129 + tc8 + 2 * p + 1] = lrelu(v.y + b0r[2 * p + 1]);
            }
        }
        __syncthreads();

        zero_acc(acc);
        mma_tile<128, 129>(H, Ws1, tr8, tc8, acc);
        __syncthreads();
#pragma unroll
        for (int i = 0; i < 8; i++) {
            int gr = row0 + tr8 + i;
            if (gr >= N_FLOW) continue;
            float inv = 1.f / fmaxf(__ldg(cnt + gr), 1.f);
            float4 p0 = *(const float4*)(agg2 + (size_t)gr * 128 + tc8);
            float4 p1 = *(const float4*)(agg2 + (size_t)gr * 128 + tc8 + 4);
            float pv[8] = {p0.x, p0.y, p0.z, p0.w, p1.x, p1.y, p1.z, p1.w};
#pragma unroll
            for (int p = 0; p < 4; p++) {
                float2 v = *reinterpret_cast<float2*>(&acc[i][p]);
                H[(tr8 + i) * 129 + tc8 + 2 * p]     = lrelu(v.x + pv[2 * p] * inv + b1r[2 * p]);
                H[(tr8 + i) * 129 + tc8 + 2 * p + 1] = lrelu(v.y + pv[2 * p + 1] * inv + b1r[2 * p + 1]);
            }
        }
        __syncthreads();

        ull acc3[4][2];
#pragma unroll
        for (int i = 0; i < 4; i++) { acc3[i][0] = 0ull; acc3[i][1] = 0ull; }
#pragma unroll 4
        for (int kk = 0; kk < 128; kk++) {
            float4 wv = __ldg((const float4*)(Wo + kk * 32 + c4));
            ull wx, wy;
            asm("mov.b64 %0, {%1, %2};" : "=l"(wx) : "f"(wv.x), "f"(wv.y));
            asm("mov.b64 %0, {%1, %2};" : "=l"(wy) : "f"(wv.z), "f"(wv.w));
#pragma unroll
            for (int i = 0; i < 4; i++) {
                ull ad = dup2(H[(r4 + i) * 129 + kk]);
                ffma2(acc3[i][0], ad, wx);
                ffma2(acc3[i][1], ad, wy);
            }
        }
#pragma unroll
        for (int i = 0; i < 4; i++) {
            int gr = row0 + r4 + i;
            if (gr >= N_FLOW) continue;
            float2 v0 = *reinterpret_cast<float2*>(&acc3[i][0]);
            float2 v1 = *reinterpret_cast<float2*>(&acc3[i][1]);
            *(float4*)(out + (size_t)gr * 32 + c4) =
                make_float4(v0.x + bor[0], v0.y + bor[1], v1.x + bor[2], v1.y + bor[3]);
        }
    }
#endif
}

// ---------------- host launcher (multi-stream graph fork/join + sc128/flow overlap) ----------------
extern "C" void kernel_launch(void* const* d_in, const int* in_sizes, int n_in,
                              void* d_out, int out_size)
{
    const float* x_host  = (const float*)d_in[0];
    const float* x_flow  = (const float*)d_in[1];
    const int*   src_hf  = (const int*)d_in[2];
    const int*   dst_hf  = (const int*)d_in[3];
    const int*   src_fh  = (const int*)d_in[4];
    const int*   dst_fh  = (const int*)d_in[5];
    const float* W0_hf_l = (const float*)d_in[6];
    const float* W0_hf_r = (const float*)d_in[7];
    const float* b0_hf   = (const float*)d_in[8];
    const float* W0_fh_l = (const float*)d_in[9];
    const float* W0_fh_r = (const float*)d_in[10];
    const float* b0_fh   = (const float*)d_in[11];
    const float* W1_hf_l = (const float*)d_in[12];
    const float* W1_hf_r = (const float*)d_in[13];
    const float* b1_hf   = (const float*)d_in[14];
    // d_in[15..17] unused (g_host discarded)
    const float* W_out   = (const float*)d_in[18];
    const float* b_out   = (const float*)d_in[19];
    float* out = (float*)d_out;

    float *aggX, *cntF, *aggH, *cntH, *th1, *agg2;
    cudaGetSymbolAddress((void**)&aggX, g_aggX);
    cudaGetSymbolAddress((void**)&cntF, g_cntF);
    cudaGetSymbolAddress((void**)&aggH, g_aggH);
    cudaGetSymbolAddress((void**)&cntH, g_cntH);
    cudaGetSymbolAddress((void**)&th1,  g_th1);
    cudaGetSymbolAddress((void**)&agg2, g_agg2);

    cudaFuncSetAttribute(k_host, cudaFuncAttributeMaxDynamicSharedMemorySize, HOST_SMEM_REQ);
    cudaFuncSetAttribute(k_flow_tc, cudaFuncAttributeMaxDynamicSharedMemorySize, FLOW_SMEM_REQ);

    static cudaStream_t s1 = nullptr, s2 = nullptr;
    static cudaEvent_t evFork = nullptr, evFh = nullptr, evHost = nullptr, evHf = nullptr,
                       evA2 = nullptr, evSc = nullptr;
    if (s1 == nullptr) {
        cudaStreamCreateWithFlags(&s1, cudaStreamNonBlocking);
        cudaStreamCreateWithFlags(&s2, cudaStreamNonBlocking);
        cudaEventCreateWithFlags(&evFork, cudaEventDisableTiming);
        cudaEventCreateWithFlags(&evFh, cudaEventDisableTiming);
        cudaEventCreateWithFlags(&evHost, cudaEventDisableTiming);
        cudaEventCreateWithFlags(&evHf, cudaEventDisableTiming);
        cudaEventCreateWithFlags(&evA2, cudaEventDisableTiming);
        cudaEventCreateWithFlags(&evSc, cudaEventDisableTiming);
    }

    // Fork side streams off the origin stream.
    cudaEventRecord(evFork, 0);
    cudaStreamWaitEvent(s1, evFork, 0);
    cudaStreamWaitEvent(s2, evFork, 0);

    // Origin: zero fh-aggregates -> fh-scatter -> host chain (tcgen05)
    k_zero_fh<<<256, 256>>>();
    k_scatter64<<<(NE + 15) / 16, 256>>>(x_flow, src_fh, dst_fh, aggH, cntH);
    cudaEventRecord(evFh, 0);
    k_host<<<157, 256, HOST_SMEM_REQ>>>(aggH, cntH, x_host,
                                        W0_fh_l, W0_fh_r, b0_fh, W1_hf_l, th1);
    cudaEventRecord(evHost, 0);

    // s1: zero hf-aggregates, then hf-scatter AFTER fh-scatter finishes (runs under k_host)
    k_zero_hf<<<1024, 256, 0, s1>>>();
    cudaStreamWaitEvent(s1, evFh, 0);
    k_scatter64<<<(NE + 15) / 16, 256, 0, s1>>>(x_host, src_hf, dst_hf, aggX, cntF);
    cudaEventRecord(evHf, s1);

    // s2: zero agg2 + reset counter; then 128-dim scatter AFTER host (concurrent with flow)
    k_zero_a2<<<2048, 256, 0, s2>>>();
    cudaEventRecord(evA2, s2);
    cudaStreamWaitEvent(s2, evHost, 0);
    k_scatter128<<<SC128_GRID, 256, 0, s2>>>(th1, src_hf, dst_hf, agg2);
    cudaEventRecord(evSc, s2);

    // Origin: flow starts after hf-scatter + agg2-zero; epi2 gated in-kernel on sc128 completion
    cudaStreamWaitEvent(0, evHf, 0);
    cudaStreamWaitEvent(0, evA2, 0);
    k_flow_tc<<<148, 256, FLOW_SMEM_REQ>>>(x_flow, aggX, agg2, cntF,
                                           W0_hf_r, W0_hf_l, b0_hf,
                                           W1_hf_r, b1_hf,
                                           W_out, b_out, out);
    // Join s2's tail (sc128) into the origin stream AFTER the flow launch so the
    // capture graph is fully joined without serializing flow behind sc128.
    cudaStreamWaitEvent(0, evSc, 0);
}